// round 2
// baseline (speedup 1.0000x reference)
#include <cuda_runtime.h>
#include <cuda_bf16.h>

#define BB    8
#define SS    2048
#define DIN   2048
#define DOUT  2048
#define KK    16

// Scratch (r-pair-interleaved mixed weights + intermediate z)
__device__ __align__(16) float g_AP[BB * 8 * DIN * 2];   // [b][rp][i][c], c: r=2rp+c
__device__ __align__(16) float g_BP[BB * 8 * DOUT * 2];  // [b][rp][o][c]
__device__ __align__(16) float g_z[BB * SS * 16];        // [b][s][r]

typedef unsigned long long u64;

__device__ __forceinline__ void ffma2(u64 &d, u64 a, u64 b) {
    asm("fma.rn.f32x2 %0, %1, %2, %3;" : "=l"(d) : "l"(a), "l"(b), "l"(d));
}
__device__ __forceinline__ u64 add2(u64 a, u64 b) {
    u64 d; asm("add.rn.f32x2 %0, %1, %2;" : "=l"(d) : "l"(a), "l"(b)); return d;
}
__device__ __forceinline__ float2 unpack2(u64 v) {
    float2 f; asm("mov.b64 {%0, %1}, %2;" : "=f"(f.x), "=f"(f.y) : "l"(v)); return f;
}
__device__ __forceinline__ u64 splat(float x) {
    u64 d; asm("mov.b64 %0, {%1, %1};" : "=l"(d) : "f"(x)); return d;
}

// ---------------------------------------------------------------------------
// Kernel 1: mix banks -> r-pair-interleaved layouts.
//   g_AP[b][rp][i][c] = sum_k alpha[b,k] * A_bank[k][2rp+c][i]
//   g_BP[b][rp][o][c] = sum_k alpha[b,k] * B_bank[k][o][2rp+c]
// 384 blocks x 256 = 98304 threads: 32768 for A (i-quad each), 65536 for B
// (o x r-quad each). All bank loads are fully coalesced float4.
// ---------------------------------------------------------------------------
__global__ void __launch_bounds__(256) mix_kernel(const float* __restrict__ alpha,
                                                  const float* __restrict__ Abank,
                                                  const float* __restrict__ Bbank) {
    int t = blockIdx.x * blockDim.x + threadIdx.x;
    if (t < 32768) {
        // A part: b(8) x rp(8) x iq(512)
        int b = t >> 12;
        int rem = t & 4095;
        int rp = rem >> 9;
        int iq = (rem & 511) << 2;                 // i quad base
        const float* a0 = Abank + (size_t)(2 * rp) * DIN + iq;       // r=2rp row
        const float* a1 = Abank + (size_t)(2 * rp + 1) * DIN + iq;   // r=2rp+1 row
        const float* al = alpha + b * KK;
        float4 acc0 = make_float4(0.f, 0.f, 0.f, 0.f);
        float4 acc1 = make_float4(0.f, 0.f, 0.f, 0.f);
#pragma unroll
        for (int k = 0; k < KK; k++) {
            float a = al[k];
            float4 v0 = *(const float4*)(a0 + (size_t)k * 16 * DIN);
            float4 v1 = *(const float4*)(a1 + (size_t)k * 16 * DIN);
            acc0.x += a * v0.x; acc0.y += a * v1.x;   // i=iq   : c0,c1
            acc0.z += a * v0.y; acc0.w += a * v1.y;   // i=iq+1
            acc1.x += a * v0.z; acc1.y += a * v1.z;   // i=iq+2
            acc1.z += a * v0.w; acc1.w += a * v1.w;   // i=iq+3
        }
        float* dst = g_AP + ((size_t)(b * 8 + rp) * DIN + iq) * 2;
        *(float4*)(dst)     = acc0;
        *(float4*)(dst + 4) = acc1;
    } else {
        // B part: b(8) x o(2048) x q(4); thread owns r-quad 4q..4q+3 for one o
        int t2 = t - 32768;
        int b = t2 >> 13;
        int rem = t2 & 8191;
        int o = rem >> 2;
        int q = rem & 3;
        const float* bb = Bbank + (size_t)o * 16 + 4 * q;   // B_bank[k][o][4q], k-stride 2048*16
        const float* al = alpha + b * KK;
        float4 acc = make_float4(0.f, 0.f, 0.f, 0.f);
#pragma unroll
        for (int k = 0; k < KK; k++) {
            float a = al[k];
            float4 v = *(const float4*)(bb + (size_t)k * DOUT * 16);
            acc.x += a * v.x; acc.y += a * v.y; acc.z += a * v.z; acc.w += a * v.w;
        }
        *(float2*)(g_BP + ((size_t)(b * 8 + 2 * q)     * DOUT + o) * 2) = make_float2(acc.x, acc.y);
        *(float2*)(g_BP + ((size_t)(b * 8 + 2 * q + 1) * DOUT + o) * 2) = make_float2(acc.z, acc.w);
    }
}

// ---------------------------------------------------------------------------
// Kernel 2: z[b][s][r] = sum_i AP[b][r/2][i][r&1] * h[b][s][i]
// 512 CTAs (8 b x 64 s-tiles of 32) x 256 threads = 8 warps x 4 s-rows.
// Lane owns 2 consecutive i per 64-i chunk. Accumulators are f32x2 over
// r-pairs: acc[4 s][8 rp] = 64 regs — no spills.
// ---------------------------------------------------------------------------
__global__ void __launch_bounds__(256, 2) z_kernel(const float* __restrict__ h) {
    __shared__ u64 red[8][32][17];   // [warp][s*8+rp][lane<16], padded vs bank conflicts

    int b = blockIdx.x >> 6;
    int stile = (blockIdx.x & 63) << 5;
    int warp = threadIdx.x >> 5;
    int lane = threadIdx.x & 31;
    int s0 = stile + warp * 4;

    const float* hp = h + (size_t)(b * SS + s0) * DIN + 2 * lane;
    const float* ap = g_AP + (size_t)b * 8 * DIN * 2 + 4 * lane;

    u64 acc[4][8];
#pragma unroll
    for (int s = 0; s < 4; s++)
#pragma unroll
        for (int rp = 0; rp < 8; rp++) acc[s][rp] = 0ull;

#pragma unroll 1
    for (int c = 0; c < DIN / 64; c++) {
        int off = c * 64;
        u64 hs[4][2];
#pragma unroll
        for (int s = 0; s < 4; s++) {
            u64 hv = *(const u64*)(hp + (size_t)s * DIN + off);
            float2 hf = unpack2(hv);
            hs[s][0] = splat(hf.x);
            hs[s][1] = splat(hf.y);
        }
#pragma unroll
        for (int rp = 0; rp < 8; rp++) {
            ulonglong2 av = *(const ulonglong2*)(ap + ((size_t)rp * DIN + off) * 2);
#pragma unroll
            for (int s = 0; s < 4; s++) {
                ffma2(acc[s][rp], av.x, hs[s][0]);   // i0: (r=2rp, 2rp+1)
                ffma2(acc[s][rp], av.y, hs[s][1]);   // i1
            }
        }
    }

    // Cross-lane reduce: one xor-16 round on packed pairs, then smem.
#pragma unroll
    for (int s = 0; s < 4; s++)
#pragma unroll
        for (int rp = 0; rp < 8; rp++) {
            u64 w = acc[s][rp];
            u64 o = __shfl_xor_sync(0xffffffffu, w, 16);
            w = add2(w, o);
            if (lane < 16) red[warp][s * 8 + rp][lane] = w;
        }
    __syncthreads();

    // Phase 2: 256 rows (8 warps x 32 vals), 16 partials each.
    int w = threadIdx.x >> 5;
    int v = threadIdx.x & 31;
    u64 sum = red[w][v][0];
#pragma unroll
    for (int j = 1; j < 16; j++) sum = add2(sum, red[w][v][j]);
    float2 f = unpack2(sum);
    int s = stile + w * 4 + (v >> 3);
    int rp = v & 7;
    *(float2*)(g_z + ((size_t)(b * SS + s) * 16 + 2 * rp)) = f;
}

// ---------------------------------------------------------------------------
// Kernel 3: delta[b][s][o] = sum_r BP[b][r/2][o][r&1] * z[b][s][r]
// 2048 CTAs (8 b x 32 s-tiles of 64 x 8 o-tiles of 256) x 256 threads.
// Warp owns 8 s x 256 o; z tile (64 s x 16 r) staged in smem, read via
// broadcast LDS.64. acc[8 s][2 o] f32x2 over r-pairs = 32 regs.
// ---------------------------------------------------------------------------
__global__ void __launch_bounds__(256, 3) delta_kernel(float* __restrict__ out) {
    __shared__ float zs[64 * 16];

    int ot = blockIdx.x & 7;
    int st = (blockIdx.x >> 3) & 31;
    int b = blockIdx.x >> 8;
    int warp = threadIdx.x >> 5;
    int lane = threadIdx.x & 31;
    int s0 = st * 64;
    int o0 = ot * 256;

    // Stage z tile: 64 s x 16 r = 1024 floats, one float4 per thread.
    *(float4*)(zs + threadIdx.x * 4) =
        *(const float4*)(g_z + (size_t)(b * SS + s0) * 16 + threadIdx.x * 4);
    __syncthreads();

    const float* zrow = zs + (warp * 8) * 16;
    const float* bp = g_BP + ((size_t)(b * 8) * DOUT + o0 + 2 * lane) * 2;
    float* op = out + (size_t)(b * SS + s0 + warp * 8) * DOUT + o0 + 2 * lane;

#pragma unroll
    for (int ch = 0; ch < 4; ch++) {
        u64 acc[8][2];
#pragma unroll
        for (int s = 0; s < 8; s++) { acc[s][0] = 0ull; acc[s][1] = 0ull; }

#pragma unroll
        for (int rp = 0; rp < 8; rp++) {
            ulonglong2 bv = *(const ulonglong2*)(bp + ((size_t)rp * DOUT + ch * 64) * 2);
#pragma unroll
            for (int s = 0; s < 8; s++) {
                u64 zv = *(const u64*)(zrow + s * 16 + 2 * rp);   // broadcast LDS.64
                ffma2(acc[s][0], bv.x, zv);   // o even
                ffma2(acc[s][1], bv.y, zv);   // o odd
            }
        }

#pragma unroll
        for (int s = 0; s < 8; s++) {
            float2 r0 = unpack2(acc[s][0]);
            float2 r1 = unpack2(acc[s][1]);
            *(float2*)(op + (size_t)s * DOUT + ch * 64) =
                make_float2(r0.x + r0.y, r1.x + r1.y);
        }
    }
}

// ---------------------------------------------------------------------------
extern "C" void kernel_launch(void* const* d_in, const int* in_sizes, int n_in,
                              void* d_out, int out_size) {
    const float* h     = (const float*)d_in[0];   // [8,2048,2048]
    const float* alpha = (const float*)d_in[1];   // [8,16]
    const float* Abank = (const float*)d_in[2];   // [16,16,2048]
    const float* Bbank = (const float*)d_in[3];   // [16,2048,16]
    float* out = (float*)d_out;                   // [8,2048,2048]

    mix_kernel<<<384, 256>>>(alpha, Abank, Bbank);
    z_kernel<<<512, 256>>>(h);
    delta_kernel<<<2048, 256>>>(out);
}

// round 3
// speedup vs baseline: 1.4078x; 1.4078x over previous
#include <cuda_runtime.h>
#include <cuda_bf16.h>

#define BB    8
#define SS    2048
#define DIN   2048
#define DOUT  2048
#define KK    16
#define RR    16

// Scratch
__device__ __align__(16) float g_Am[BB * RR * DIN];    // [b][r][i]
__device__ __align__(16) float g_Bm[BB * RR * DOUT];   // [b][r][o]  (transposed B_mixed)
__device__ __align__(16) float g_z[BB * SS * RR];      // [b][s][r]

// ---------------------------------------------------------------------------
// Kernel 1: mix the banks.
//   g_Am[b][r][i] = sum_k alpha[b,k] * A_bank[k][r][i]
//   g_Bm[b][r][o] = sum_k alpha[b,k] * B_bank[k][o][r]
// 512 blocks x 256 thr. First 65536 threads: A (one float4 of i each).
// Next 65536: B (one o, r-quad each; coalesced float4 reads, 4 coalesced
// scalar writes).
// ---------------------------------------------------------------------------
__global__ void __launch_bounds__(256) mix_kernel(const float* __restrict__ alpha,
                                                  const float* __restrict__ Abank,
                                                  const float* __restrict__ Bbank) {
    int t = blockIdx.x * blockDim.x + threadIdx.x;
    if (t < 65536) {
        // A: b(8) x r(16) x iq(512)
        int b = t >> 13;
        int rem = t & 8191;
        int r = rem >> 9;
        int i = (rem & 511) << 2;
        const float* ab = Abank + (size_t)r * DIN + i;
        const float* al = alpha + b * KK;
        float4 acc = make_float4(0.f, 0.f, 0.f, 0.f);
#pragma unroll
        for (int k = 0; k < KK; k++) {
            float a = al[k];
            float4 v = *(const float4*)(ab + (size_t)k * RR * DIN);
            acc.x += a * v.x; acc.y += a * v.y; acc.z += a * v.z; acc.w += a * v.w;
        }
        *(float4*)(g_Am + ((size_t)(b * RR + r) * DIN + i)) = acc;
    } else {
        // B: b(8) x o(2048) x q(4): thread reduces B_bank[k][o][4q..4q+3]
        int t2 = t - 65536;
        int b = t2 >> 13;
        int rem = t2 & 8191;
        int q = rem >> 11;               // r-quad index 0..3
        int o = rem & 2047;              // lane-consecutive o -> coalesced
        const float* bb = Bbank + (size_t)o * RR + 4 * q;
        const float* al = alpha + b * KK;
        float4 acc = make_float4(0.f, 0.f, 0.f, 0.f);
#pragma unroll
        for (int k = 0; k < KK; k++) {
            float a = al[k];
            float4 v = *(const float4*)(bb + (size_t)k * DOUT * RR);
            acc.x += a * v.x; acc.y += a * v.y; acc.z += a * v.z; acc.w += a * v.w;
        }
        float* dst = g_Bm + (size_t)b * RR * DOUT + o;
        dst[(4 * q + 0) * DOUT] = acc.x;
        dst[(4 * q + 1) * DOUT] = acc.y;
        dst[(4 * q + 2) * DOUT] = acc.z;
        dst[(4 * q + 3) * DOUT] = acc.w;
    }
}

// ---------------------------------------------------------------------------
// Kernel 2: z[b][s][r] = sum_i Am[b][r][i] * h[b][s][i]
// 512 CTAs (8 b x 64 s-tiles of 32) x 256 thr = 8 warps x 4 s-rows.
// Lane owns an i-quad per 128-i chunk. Pure scalar FFMA, acc[4][16] = 64 regs.
// ---------------------------------------------------------------------------
__global__ void __launch_bounds__(256, 2) z_kernel(const float* __restrict__ h) {
    __shared__ float red[8][64][17];

    int b = blockIdx.x >> 6;
    int stile = (blockIdx.x & 63) << 5;
    int warp = threadIdx.x >> 5;
    int lane = threadIdx.x & 31;
    int s0 = stile + warp * 4;

    const float* hp = h + (size_t)(b * SS + s0) * DIN + 4 * lane;
    const float* ap = g_Am + (size_t)b * RR * DIN + 4 * lane;

    float acc[4][16];
#pragma unroll
    for (int s = 0; s < 4; s++)
#pragma unroll
        for (int r = 0; r < 16; r++) acc[s][r] = 0.f;

#pragma unroll 1
    for (int c = 0; c < DIN / 128; c++) {
        int off = c * 128;
        float4 hv[4];
#pragma unroll
        for (int s = 0; s < 4; s++)
            hv[s] = *(const float4*)(hp + (size_t)s * DIN + off);
#pragma unroll
        for (int r = 0; r < 16; r++) {
            float4 av = *(const float4*)(ap + (size_t)r * DIN + off);
#pragma unroll
            for (int s = 0; s < 4; s++) {
                acc[s][r] += av.x * hv[s].x;
                acc[s][r] += av.y * hv[s].y;
                acc[s][r] += av.z * hv[s].z;
                acc[s][r] += av.w * hv[s].w;
            }
        }
    }

    // Cross-lane reduce: one xor-16 round, then smem transpose-reduce.
#pragma unroll
    for (int s = 0; s < 4; s++)
#pragma unroll
        for (int r = 0; r < 16; r++) {
            float v = acc[s][r];
            v += __shfl_xor_sync(0xffffffffu, v, 16);
            if (lane < 16) red[warp][s * 16 + r][lane] = v;
        }
    __syncthreads();

    // 512 outputs, 2 per thread; 16 partials each. Coalesced STG.32.
#pragma unroll
    for (int half = 0; half < 2; half++) {
        int row = threadIdx.x + half * 256;
        int w = row >> 6;
        int v = row & 63;
        float sum = 0.f;
#pragma unroll
        for (int j = 0; j < 16; j++) sum += red[w][v][j];
        int s = stile + w * 4 + (v >> 4);
        int r = v & 15;
        g_z[((size_t)(b * SS + s)) * RR + r] = sum;
    }
}

// ---------------------------------------------------------------------------
// Kernel 3: delta[b][s][o] = sum_r Bm[b][r][o] * z[b][s][r]
// 2048 CTAs (8 b x 32 s-tiles of 64 x 8 o-tiles of 256) x 256 thr.
// Warp: 8 s x 256 o (two 128-o halves). z tile staged in smem, read via
// broadcast LDS.32 (1 LDS per 4 FFMA). acc[8][4] = 32 regs per half.
// ---------------------------------------------------------------------------
__global__ void __launch_bounds__(256, 3) delta_kernel(float* __restrict__ out) {
    __shared__ float zs[64 * 16];

    int ot = blockIdx.x & 7;
    int st = (blockIdx.x >> 3) & 31;
    int b = blockIdx.x >> 8;
    int warp = threadIdx.x >> 5;
    int lane = threadIdx.x & 31;
    int s0 = st * 64;
    int o0 = ot * 256;

    // Stage z tile: 64 s x 16 r = 4 KB, one float4 per thread, coalesced.
    *(float4*)(zs + threadIdx.x * 4) =
        *(const float4*)(g_z + (size_t)(b * SS + s0) * RR + threadIdx.x * 4);
    __syncthreads();

    const float* zrow = zs + (warp * 8) * 16;
    const float* bp = g_Bm + (size_t)b * RR * DOUT + o0 + 4 * lane;
    float* op = out + (size_t)(b * SS + s0 + warp * 8) * DOUT + o0 + 4 * lane;

#pragma unroll
    for (int half = 0; half < 2; half++) {
        int oo = half * 128;
        float4 acc[8];
#pragma unroll
        for (int s = 0; s < 8; s++) acc[s] = make_float4(0.f, 0.f, 0.f, 0.f);

#pragma unroll
        for (int r = 0; r < RR; r++) {
            float4 bv = *(const float4*)(bp + (size_t)r * DOUT + oo);
#pragma unroll
            for (int s = 0; s < 8; s++) {
                float zv = zrow[s * 16 + r];         // broadcast LDS.32
                acc[s].x += bv.x * zv;
                acc[s].y += bv.y * zv;
                acc[s].z += bv.z * zv;
                acc[s].w += bv.w * zv;
            }
        }

#pragma unroll
        for (int s = 0; s < 8; s++)
            *(float4*)(op + (size_t)s * DOUT + oo) = acc[s];
    }
}

// ---------------------------------------------------------------------------
extern "C" void kernel_launch(void* const* d_in, const int* in_sizes, int n_in,
                              void* d_out, int out_size) {
    const float* h     = (const float*)d_in[0];   // [8,2048,2048]
    const float* alpha = (const float*)d_in[1];   // [8,16]
    const float* Abank = (const float*)d_in[2];   // [16,16,2048]
    const float* Bbank = (const float*)d_in[3];   // [16,2048,16]
    float* out = (float*)d_out;                   // [8,2048,2048]

    mix_kernel<<<512, 256>>>(alpha, Abank, Bbank);
    z_kernel<<<512, 256>>>(h);
    delta_kernel<<<2048, 256>>>(out);
}

// round 4
// speedup vs baseline: 2.0150x; 1.4314x over previous
#include <cuda_runtime.h>
#include <cuda_bf16.h>

#define BB    8
#define SS    2048
#define DIN   2048
#define DOUT  2048
#define KK    16
#define RR    16

// Scratch
__device__ __align__(16) float g_Am[BB * RR * DIN];    // [b][r][i]
__device__ __align__(16) float g_Bm[BB * RR * DOUT];   // [b][r][o]
__device__ __align__(16) float g_z[BB * SS * RR];      // [b][s][r]

// ---------------------------------------------------------------------------
// Kernel 1: mix banks, all 8 batches per thread (banks read once).
//   g_Am[b][r][i] = sum_k alpha[b,k] * A_bank[k][r][i]
//   g_Bm[b][r][o] = sum_k alpha[b,k] * B_bank[k][o][r]
// 64 blocks x 256 thr = 16384 threads: first 8192 cover A (r x i-quad),
// next 8192 cover B (r-quad x o).
// ---------------------------------------------------------------------------
__global__ void __launch_bounds__(256, 2) mix_kernel(const float* __restrict__ alpha,
                                                     const float* __restrict__ Abank,
                                                     const float* __restrict__ Bbank) {
    __shared__ float sal[BB * KK];
    if (threadIdx.x < BB * KK) sal[threadIdx.x] = alpha[threadIdx.x];
    __syncthreads();

    int t = blockIdx.x * blockDim.x + threadIdx.x;
    if (t < 8192) {
        // A: r(16) x iq(512)
        int r = t >> 9;
        int i = (t & 511) << 2;
        const float* ab = Abank + (size_t)r * DIN + i;
        float4 acc[BB];
#pragma unroll
        for (int b = 0; b < BB; b++) acc[b] = make_float4(0.f, 0.f, 0.f, 0.f);
#pragma unroll
        for (int k = 0; k < KK; k++) {
            float4 v = *(const float4*)(ab + (size_t)k * RR * DIN);
#pragma unroll
            for (int b = 0; b < BB; b++) {
                float a = sal[b * KK + k];
                acc[b].x += a * v.x; acc[b].y += a * v.y;
                acc[b].z += a * v.z; acc[b].w += a * v.w;
            }
        }
#pragma unroll
        for (int b = 0; b < BB; b++)
            *(float4*)(g_Am + ((size_t)(b * RR + r) * DIN + i)) = acc[b];
    } else {
        // B: q(4) x o(2048); thread reduces B_bank[k][o][4q..4q+3] over k
        int t2 = t - 8192;
        int q = t2 >> 11;
        int o = t2 & 2047;
        const float* bb = Bbank + (size_t)o * RR + 4 * q;
        float4 acc[BB];
#pragma unroll
        for (int b = 0; b < BB; b++) acc[b] = make_float4(0.f, 0.f, 0.f, 0.f);
#pragma unroll
        for (int k = 0; k < KK; k++) {
            float4 v = *(const float4*)(bb + (size_t)k * DOUT * RR);
#pragma unroll
            for (int b = 0; b < BB; b++) {
                float a = sal[b * KK + k];
                acc[b].x += a * v.x; acc[b].y += a * v.y;
                acc[b].z += a * v.z; acc[b].w += a * v.w;
            }
        }
#pragma unroll
        for (int b = 0; b < BB; b++) {
            float* dst = g_Bm + (size_t)b * RR * DOUT + o;
            dst[(4 * q + 0) * DOUT] = acc[b].x;
            dst[(4 * q + 1) * DOUT] = acc[b].y;
            dst[(4 * q + 2) * DOUT] = acc[b].z;
            dst[(4 * q + 3) * DOUT] = acc[b].w;
        }
    }
}

// ---------------------------------------------------------------------------
// Kernel 2: z[b][s][r] = sum_i Am[b][r][i] * h[b][s][i]
// 512 CTAs (8 b x 64 s-tiles of 32) x 256 thr = 8 warps x 4 s-rows.
// Lane owns an i-quad per 128-i chunk. r processed in PAIRS to cap live
// loads: live ~ acc(64) + hv(16) + av(8) + ptrs ≈ 100 regs < 128 cap.
// ---------------------------------------------------------------------------
__global__ void __launch_bounds__(256, 2) z_kernel(const float* __restrict__ h) {
    __shared__ float red[8][64][17];

    int b = blockIdx.x >> 6;
    int stile = (blockIdx.x & 63) << 5;
    int warp = threadIdx.x >> 5;
    int lane = threadIdx.x & 31;
    int s0 = stile + warp * 4;

    const float* hp = h + (size_t)(b * SS + s0) * DIN + 4 * lane;
    const float* ap = g_Am + (size_t)b * RR * DIN + 4 * lane;

    float acc[4][16];
#pragma unroll
    for (int s = 0; s < 4; s++)
#pragma unroll
        for (int r = 0; r < 16; r++) acc[s][r] = 0.f;

#pragma unroll 1
    for (int c = 0; c < DIN / 128; c++) {
        int off = c * 128;
        float4 hv[4];
#pragma unroll
        for (int s = 0; s < 4; s++)
            hv[s] = *(const float4*)(hp + (size_t)s * DIN + off);

#pragma unroll
        for (int rg = 0; rg < 8; rg++) {          // r pairs: bounded liveness
            float4 av0 = *(const float4*)(ap + (size_t)(2 * rg)     * DIN + off);
            float4 av1 = *(const float4*)(ap + (size_t)(2 * rg + 1) * DIN + off);
#pragma unroll
            for (int s = 0; s < 4; s++) {
                acc[s][2 * rg]     += av0.x * hv[s].x;
                acc[s][2 * rg]     += av0.y * hv[s].y;
                acc[s][2 * rg]     += av0.z * hv[s].z;
                acc[s][2 * rg]     += av0.w * hv[s].w;
                acc[s][2 * rg + 1] += av1.x * hv[s].x;
                acc[s][2 * rg + 1] += av1.y * hv[s].y;
                acc[s][2 * rg + 1] += av1.z * hv[s].z;
                acc[s][2 * rg + 1] += av1.w * hv[s].w;
            }
        }
    }

    // Cross-lane reduce: one xor-16 round, then smem transpose-reduce.
#pragma unroll
    for (int s = 0; s < 4; s++)
#pragma unroll
        for (int r = 0; r < 16; r++) {
            float v = acc[s][r];
            v += __shfl_xor_sync(0xffffffffu, v, 16);
            if (lane < 16) red[warp][s * 16 + r][lane] = v;
        }
    __syncthreads();

#pragma unroll
    for (int half = 0; half < 2; half++) {
        int row = threadIdx.x + half * 256;
        int w = row >> 6;
        int v = row & 63;
        float sum = 0.f;
#pragma unroll
        for (int j = 0; j < 16; j++) sum += red[w][v][j];
        int s = stile + w * 4 + (v >> 4);
        int r = v & 15;
        g_z[((size_t)(b * SS + s)) * RR + r] = sum;
    }
}

// ---------------------------------------------------------------------------
// Kernel 3: delta[b][s][o] = sum_r Bm[b][r][o] * z[b][s][r]
// 2048 CTAs (8 b x 32 s-tiles of 64 x 8 o-tiles of 256) x 256 thr, occ 2
// (128-reg cap — no spills). Warp: 8 s x 256 o in two 128-o halves; r in
// pairs to bound liveness: acc(32) + bv(8) + z smem broadcasts ≈ 60 regs.
// ---------------------------------------------------------------------------
__global__ void __launch_bounds__(256, 2) delta_kernel(float* __restrict__ out) {
    __shared__ float zs[64 * 16];

    int ot = blockIdx.x & 7;
    int st = (blockIdx.x >> 3) & 31;
    int b = blockIdx.x >> 8;
    int warp = threadIdx.x >> 5;
    int lane = threadIdx.x & 31;
    int s0 = st * 64;
    int o0 = ot * 256;

    *(float4*)(zs + threadIdx.x * 4) =
        *(const float4*)(g_z + (size_t)(b * SS + s0) * RR + threadIdx.x * 4);
    __syncthreads();

    const float* zrow = zs + (warp * 8) * 16;
    const float* bp = g_Bm + (size_t)b * RR * DOUT + o0 + 4 * lane;
    float* op = out + (size_t)(b * SS + s0 + warp * 8) * DOUT + o0 + 4 * lane;

#pragma unroll
    for (int half = 0; half < 2; half++) {
        int oo = half * 128;
        float4 acc[8];
#pragma unroll
        for (int s = 0; s < 8; s++) acc[s] = make_float4(0.f, 0.f, 0.f, 0.f);

#pragma unroll
        for (int rg = 0; rg < 8; rg++) {          // r pairs: bounded liveness
            float4 bv0 = *(const float4*)(bp + (size_t)(2 * rg)     * DOUT + oo);
            float4 bv1 = *(const float4*)(bp + (size_t)(2 * rg + 1) * DOUT + oo);
#pragma unroll
            for (int s = 0; s < 8; s++) {
                float z0 = zrow[s * 16 + 2 * rg];
                float z1 = zrow[s * 16 + 2 * rg + 1];
                acc[s].x += bv0.x * z0;
                acc[s].y += bv0.y * z0;
                acc[s].z += bv0.z * z0;
                acc[s].w += bv0.w * z0;
                acc[s].x += bv1.x * z1;
                acc[s].y += bv1.y * z1;
                acc[s].z += bv1.z * z1;
                acc[s].w += bv1.w * z1;
            }
        }

#pragma unroll
        for (int s = 0; s < 8; s++)
            *(float4*)(op + (size_t)s * DOUT + oo) = acc[s];
    }
}

// ---------------------------------------------------------------------------
extern "C" void kernel_launch(void* const* d_in, const int* in_sizes, int n_in,
                              void* d_out, int out_size) {
    const float* h     = (const float*)d_in[0];   // [8,2048,2048]
    const float* alpha = (const float*)d_in[1];   // [8,16]
    const float* Abank = (const float*)d_in[2];   // [16,16,2048]
    const float* Bbank = (const float*)d_in[3];   // [16,2048,16]
    float* out = (float*)d_out;                   // [8,2048,2048]

    mix_kernel<<<64, 256>>>(alpha, Abank, Bbank);
    z_kernel<<<512, 256>>>(h);
    delta_kernel<<<2048, 256>>>(out);
}

// round 6
// speedup vs baseline: 2.5317x; 1.2564x over previous
#include <cuda_runtime.h>
#include <cuda_bf16.h>
#include <cstdint>

#define BB    8
#define SS    2048
#define DIN   2048
#define DOUT  2048
#define KK    16
#define RR    16

// Scratch
__device__ __align__(16) float g_Am[BB * RR * DIN];     // [b][r][i]
__device__ __align__(16) float g_BmT[BB * DOUT * RR];   // [b][o][r]
__device__ __align__(16) float g_z[BB * SS * RR];       // [b][s][r]

// ---------------------------------------------------------------------------
// Helpers: split fp32 into bf16 hi + bf16 lo, packed for mma.sync operands.
// ---------------------------------------------------------------------------
__device__ __forceinline__ void split2(float x, float y, uint32_t &hi, uint32_t &lo) {
    __nv_bfloat16 hx = __float2bfloat16_rn(x);
    __nv_bfloat16 hy = __float2bfloat16_rn(y);
    float rx = x - __bfloat162float(hx);
    float ry = y - __bfloat162float(hy);
    __nv_bfloat162 h2 = __halves2bfloat162(hx, hy);                 // low = x-elem
    __nv_bfloat162 l2 = __floats2bfloat162_rn(rx, ry);
    hi = *reinterpret_cast<uint32_t*>(&h2);
    lo = *reinterpret_cast<uint32_t*>(&l2);
}

__device__ __forceinline__ void mma_bf16(float &d0, float &d1, float &d2, float &d3,
                                         uint32_t a0, uint32_t a1, uint32_t b0) {
    asm("mma.sync.aligned.m16n8k8.row.col.f32.bf16.bf16.f32 "
        "{%0,%1,%2,%3}, {%4,%5}, {%6}, {%0,%1,%2,%3};"
        : "+f"(d0), "+f"(d1), "+f"(d2), "+f"(d3)
        : "r"(a0), "r"(a1), "r"(b0));
}

// ---------------------------------------------------------------------------
// Kernel 1: mix banks, all 8 batches per thread (banks read once).
//   g_Am [b][r][i] = sum_k alpha[b,k] * A_bank[k][r][i]
//   g_BmT[b][o][r] = sum_k alpha[b,k] * B_bank[k][o][r]
// ---------------------------------------------------------------------------
__global__ void __launch_bounds__(256, 2) mix_kernel(const float* __restrict__ alpha,
                                                     const float* __restrict__ Abank,
                                                     const float* __restrict__ Bbank) {
    __shared__ float sal[BB * KK];
    if (threadIdx.x < BB * KK) sal[threadIdx.x] = alpha[threadIdx.x];
    __syncthreads();

    int t = blockIdx.x * blockDim.x + threadIdx.x;
    if (t < 8192) {
        int r = t >> 9;
        int i = (t & 511) << 2;
        const float* ab = Abank + (size_t)r * DIN + i;
        float4 acc[BB];
#pragma unroll
        for (int b = 0; b < BB; b++) acc[b] = make_float4(0.f, 0.f, 0.f, 0.f);
#pragma unroll
        for (int k = 0; k < KK; k++) {
            float4 v = *(const float4*)(ab + (size_t)k * RR * DIN);
#pragma unroll
            for (int b = 0; b < BB; b++) {
                float a = sal[b * KK + k];
                acc[b].x += a * v.x; acc[b].y += a * v.y;
                acc[b].z += a * v.z; acc[b].w += a * v.w;
            }
        }
#pragma unroll
        for (int b = 0; b < BB; b++)
            *(float4*)(g_Am + ((size_t)(b * RR + r) * DIN + i)) = acc[b];
    } else {
        int t2 = t - 8192;
        int q = t2 >> 11;
        int o = t2 & 2047;
        const float* bb = Bbank + (size_t)o * RR + 4 * q;
        float4 acc[BB];
#pragma unroll
        for (int b = 0; b < BB; b++) acc[b] = make_float4(0.f, 0.f, 0.f, 0.f);
#pragma unroll
        for (int k = 0; k < KK; k++) {
            float4 v = *(const float4*)(bb + (size_t)k * DOUT * RR);
#pragma unroll
            for (int b = 0; b < BB; b++) {
                float a = sal[b * KK + k];
                acc[b].x += a * v.x; acc[b].y += a * v.y;
                acc[b].z += a * v.z; acc[b].w += a * v.w;
            }
        }
#pragma unroll
        for (int b = 0; b < BB; b++)
            *(float4*)(g_BmT + ((size_t)(b * DOUT + o) * RR + 4 * q)) = acc[b];
    }
}

// ---------------------------------------------------------------------------
// Kernel 2: z[b][s][r] = sum_i Am[b][r][i] * h[b][s][i]   (scalar FFMA, R4)
// ---------------------------------------------------------------------------
__global__ void __launch_bounds__(256, 2) z_kernel(const float* __restrict__ h) {
    __shared__ float red[8][64][17];

    int b = blockIdx.x >> 6;
    int stile = (blockIdx.x & 63) << 5;
    int warp = threadIdx.x >> 5;
    int lane = threadIdx.x & 31;
    int s0 = stile + warp * 4;

    const float* hp = h + (size_t)(b * SS + s0) * DIN + 4 * lane;
    const float* ap = g_Am + (size_t)b * RR * DIN + 4 * lane;

    float acc[4][16];
#pragma unroll
    for (int s = 0; s < 4; s++)
#pragma unroll
        for (int r = 0; r < 16; r++) acc[s][r] = 0.f;

#pragma unroll 1
    for (int c = 0; c < DIN / 128; c++) {
        int off = c * 128;
        float4 hv[4];
#pragma unroll
        for (int s = 0; s < 4; s++)
            hv[s] = *(const float4*)(hp + (size_t)s * DIN + off);

#pragma unroll
        for (int rg = 0; rg < 8; rg++) {
            float4 av0 = *(const float4*)(ap + (size_t)(2 * rg)     * DIN + off);
            float4 av1 = *(const float4*)(ap + (size_t)(2 * rg + 1) * DIN + off);
#pragma unroll
            for (int s = 0; s < 4; s++) {
                acc[s][2 * rg]     += av0.x * hv[s].x;
                acc[s][2 * rg]     += av0.y * hv[s].y;
                acc[s][2 * rg]     += av0.z * hv[s].z;
                acc[s][2 * rg]     += av0.w * hv[s].w;
                acc[s][2 * rg + 1] += av1.x * hv[s].x;
                acc[s][2 * rg + 1] += av1.y * hv[s].y;
                acc[s][2 * rg + 1] += av1.z * hv[s].z;
                acc[s][2 * rg + 1] += av1.w * hv[s].w;
            }
        }
    }

#pragma unroll
    for (int s = 0; s < 4; s++)
#pragma unroll
        for (int r = 0; r < 16; r++) {
            float v = acc[s][r];
            v += __shfl_xor_sync(0xffffffffu, v, 16);
            if (lane < 16) red[warp][s * 16 + r][lane] = v;
        }
    __syncthreads();

#pragma unroll
    for (int half = 0; half < 2; half++) {
        int row = threadIdx.x + half * 256;
        int w = row >> 6;
        int v = row & 63;
        float sum = 0.f;
#pragma unroll
        for (int j = 0; j < 16; j++) sum += red[w][v][j];
        int s = stile + w * 4 + (v >> 4);
        int r = v & 15;
        g_z[((size_t)(b * SS + s)) * RR + r] = sum;
    }
}

// ---------------------------------------------------------------------------
// Kernel 3: delta[b][s][o] = sum_r z[b][s][r] * BmT[b][o][r]
// via mma.sync.m16n8k8 bf16 with split (hi+lo) operands, fp32 accumulate.
// Grid: 8b x 16 st x 16 ot = 2048 CTAs. CTA = 128s x 128o, 512 thr = 16 warps,
// each warp a 16s x 64o tile (8 n-tiles x 2 k-steps x 3 split-mmas = 48 mma).
// ---------------------------------------------------------------------------
__global__ void __launch_bounds__(512, 2) delta_kernel(float* __restrict__ out) {
    __shared__ float zs[128 * 16];
    __shared__ float bs[128 * 16];

    int ot = blockIdx.x & 15;
    int st = (blockIdx.x >> 4) & 15;
    int b  = blockIdx.x >> 8;
    int s0 = st * 128;
    int o0 = ot * 128;
    int tid = threadIdx.x;

    // Stage z tile (128s x 16r) and BmT tile (128o x 16r), coalesced float4.
    *(float4*)(zs + tid * 4) =
        *(const float4*)(g_z + (size_t)(b * SS + s0) * RR + tid * 4);
    *(float4*)(bs + tid * 4) =
        *(const float4*)(g_BmT + ((size_t)b * DOUT + o0) * RR + tid * 4);
    __syncthreads();

    int w = tid >> 5;
    int lane = tid & 31;
    int gid = lane >> 2;     // group id 0..7
    int tig = lane & 3;      // thread in group
    int sw = (w & 7) * 16;   // warp s offset within CTA tile
    int ow = (w >> 3) * 64;  // warp o offset within CTA tile

    // A fragments: 2 k-steps, hi/lo, 2 regs each (rows gid and gid+8).
    uint32_t Ah[2][2], Al[2][2];
#pragma unroll
    for (int kk = 0; kk < 2; kk++) {
        float2 v0 = *(const float2*)(zs + (sw + gid)     * 16 + kk * 8 + tig * 2);
        float2 v1 = *(const float2*)(zs + (sw + gid + 8) * 16 + kk * 8 + tig * 2);
        split2(v0.x, v0.y, Ah[kk][0], Al[kk][0]);
        split2(v1.x, v1.y, Ah[kk][1], Al[kk][1]);
    }

#pragma unroll
    for (int nt = 0; nt < 8; nt++) {
        // B fragments for this n-tile: k = 2*tig+{0,1}, n = gid.
        const float* brow = bs + (ow + nt * 8 + gid) * 16 + tig * 2;
        float2 vb0 = *(const float2*)(brow);        // k-step 0
        float2 vb1 = *(const float2*)(brow + 8);    // k-step 1
        uint32_t Bh0, Bl0, Bh1, Bl1;
        split2(vb0.x, vb0.y, Bh0, Bl0);
        split2(vb1.x, vb1.y, Bh1, Bl1);

        float d0 = 0.f, d1 = 0.f, d2 = 0.f, d3 = 0.f;
        mma_bf16(d0, d1, d2, d3, Ah[0][0], Ah[0][1], Bh0);
        mma_bf16(d0, d1, d2, d3, Ah[1][0], Ah[1][1], Bh1);
        mma_bf16(d0, d1, d2, d3, Ah[0][0], Ah[0][1], Bl0);
        mma_bf16(d0, d1, d2, d3, Ah[1][0], Ah[1][1], Bl1);
        mma_bf16(d0, d1, d2, d3, Al[0][0], Al[0][1], Bh0);
        mma_bf16(d0, d1, d2, d3, Al[1][0], Al[1][1], Bh1);

        // D: c0,c1 -> (row gid, cols 2tig,2tig+1); c2,c3 -> row gid+8.
        float* op = out + ((size_t)(b * SS + s0 + sw + gid)) * DOUT
                        + o0 + ow + nt * 8 + tig * 2;
        *(float2*)op = make_float2(d0, d1);
        *(float2*)(op + (size_t)8 * DOUT) = make_float2(d2, d3);
    }
}

// ---------------------------------------------------------------------------
extern "C" void kernel_launch(void* const* d_in, const int* in_sizes, int n_in,
                              void* d_out, int out_size) {
    const float* h     = (const float*)d_in[0];   // [8,2048,2048]
    const float* alpha = (const float*)d_in[1];   // [8,16]
    const float* Abank = (const float*)d_in[2];   // [16,16,2048]
    const float* Bbank = (const float*)d_in[3];   // [16,2048,16]
    float* out = (float*)d_out;                   // [8,2048,2048]

    mix_kernel<<<64, 256>>>(alpha, Abank, Bbank);
    z_kernel<<<512, 256>>>(h);
    delta_kernel<<<2048, 512>>>(out);
}